// round 15
// baseline (speedup 1.0000x reference)
#include <cuda_runtime.h>
#include <cuda_bf16.h>
#include <cstdint>
#include <cstddef>

#define R 64        // reduced channels
#define C 256       // channels
#define HH 96
#define WW 96
#define PIX (HH*WW)
#define NG 16       // groups
#define GC 16       // group channels
#define KT 7
#define KT2 49

// x = relu(BN(W1 @ guide)) stored FRAGMENT-PACKED for m16n8k16 A-operands:
// [b][ptile 48][pixblock 12][kblock 4][lane 32][reg 4] (u32 = 2 bf16)
__device__ uint32_t g_xfh[(size_t)8 * 48 * 12 * 4 * 32 * 4];
__device__ uint32_t g_xfl[(size_t)8 * 48 * 12 * 4 * 32 * 4];

// W2 pre-packed as m16n8k16 B-fragments, hi/lo:
// [g][ks 4][ntile 8][lane 32] uint2 = {b0 (k,k+1), b1 (k+8,k+9)}
__device__ uint2 g_w2h[NG * 4 * 8 * 32];
__device__ uint2 g_w2l[NG * 4 * 8 * 32];

#define LDK 72                 // padded k-stride (bf16 elems) in smem tiles

// ---------------------------------------------------------------------------
// mma.sync m16n8k16 bf16 (row.col), fp32 accumulate (verified mapping, R5)
// ---------------------------------------------------------------------------
__device__ __forceinline__ void mma_bf16(
    float& c0, float& c1, float& c2, float& c3,
    uint32_t a0, uint32_t a1, uint32_t a2, uint32_t a3,
    uint32_t b0, uint32_t b1)
{
    asm volatile(
        "mma.sync.aligned.m16n8k16.row.col.f32.bf16.bf16.f32 "
        "{%0,%1,%2,%3}, {%4,%5,%6,%7}, {%8,%9}, {%0,%1,%2,%3};"
        : "+f"(c0), "+f"(c1), "+f"(c2), "+f"(c3)
        : "r"(a0), "r"(a1), "r"(a2), "r"(a3), "r"(b0), "r"(b1));
}
__device__ __forceinline__ void ldmat_x4(uint32_t& r0, uint32_t& r1,
                                         uint32_t& r2, uint32_t& r3, uint32_t a)
{
    asm volatile("ldmatrix.sync.aligned.m8n8.x4.shared.b16 {%0,%1,%2,%3}, [%4];"
                 : "=r"(r0), "=r"(r1), "=r"(r2), "=r"(r3) : "r"(a));
}
__device__ __forceinline__ uint32_t sptr(const void* p) {
    return (uint32_t)__cvta_generic_to_shared(p);
}
__device__ __forceinline__ void split_pack(float a, float b,
                                           uint32_t& hi, uint32_t& lo)
{
    __nv_bfloat162 h2 = __floats2bfloat162_rn(a, b);
    __nv_bfloat162 l2 = __floats2bfloat162_rn(
        a - __bfloat162float(h2.x), b - __bfloat162float(h2.y));
    hi = *(uint32_t*)&h2;
    lo = *(uint32_t*)&l2;
}

// ---------------------------------------------------------------------------
// Kernel 0: pack W2 into B-fragment layout (runs once per launch, ~4us)
// ---------------------------------------------------------------------------
__global__ void k_w2pack(const float* __restrict__ W2)
{
    int g = blockIdx.x, t = threadIdx.x;
#pragma unroll
    for (int it = 0; it < 4; ++it) {
        int idx  = it * 256 + t;             // (ks*8 + nt)*32 + lane
        int lane = idx & 31;
        int nt   = (idx >> 5) & 7;
        int ks   = idx >> 8;
        int col  = nt * 8 + (lane >> 2);
        int k    = ks * 16 + (lane & 3) * 2;
        float w00 = 0.f, w01 = 0.f, w10 = 0.f, w11 = 0.f;
        if (col < KT2) {
            const float* wp = W2 + ((size_t)g * KT2 + col) * R;
            w00 = wp[k];     w01 = wp[k + 1];
            w10 = wp[k + 8]; w11 = wp[k + 9];
        }
        uint32_t b0h, b0l, b1h, b1l;
        split_pack(w00, w01, b0h, b0l);
        split_pack(w10, w11, b1h, b1l);
        g_w2h[g * 1024 + idx] = make_uint2(b0h, b1h);
        g_w2l[g * 1024 + idx] = make_uint2(b0l, b1l);
    }
}

// ---------------------------------------------------------------------------
// Kernel 1: x = relu(BN(W1 @ guide)) via mma.sync, 3-term bf16 split.
// [unchanged from R13, ~55us]
// ---------------------------------------------------------------------------
#define C1_AH 0
#define C1_AL (192 * LDK)
#define C1_BH (2 * 192 * LDK)
#define C1_BL (2 * 192 * LDK + 64 * LDK)
#define C1_SMEM ((2 * 192 * LDK + 2 * 64 * LDK) * 2)   // 73728 bytes

__global__ __launch_bounds__(384, 2) void k_convs1(
    const float* __restrict__ guide, const float* __restrict__ W1,
    const float* __restrict__ gamma, const float* __restrict__ beta,
    const float* __restrict__ mean,  const float* __restrict__ var)
{
    extern __shared__ __nv_bfloat16 sm[];
    __nv_bfloat16* Ah = sm + C1_AH;
    __nv_bfloat16* Al = sm + C1_AL;
    __nv_bfloat16* Bh = sm + C1_BH;
    __nv_bfloat16* Bl = sm + C1_BL;
    __shared__ float sc[R], bi[R];

    const int t    = threadIdx.x;
    const int lane = t & 31;
    const int wid  = t >> 5;
    const int mw   = wid >> 1;
    const int nw   = wid & 1;
    const int b    = blockIdx.y;
    const int p0   = blockIdx.x * 192;

    if (t < R) {
        float iv = gamma[t] * rsqrtf(var[t] + 1e-5f);
        sc[t] = iv;
        bi[t] = beta[t] - mean[t] * iv;
    }

    float acc[2][4][4];
#pragma unroll
    for (int mf = 0; mf < 2; ++mf)
#pragma unroll
        for (int nf = 0; nf < 4; ++nf)
#pragma unroll
            for (int q = 0; q < 4; ++q) acc[mf][nf][q] = 0.f;

    const int l7  = lane & 7;
    const int sub = lane >> 3;
    const int a_row = mw * 32 + (sub & 1) * 8 + l7;
    const int a_col = (sub >> 1) * 8;
    const int b_row = nw * 32 + (sub >> 1) * 8 + l7;
    const int b_col = (sub & 1) * 8;
    const uint32_t ah_base = sptr(Ah) + (a_row * LDK + a_col) * 2;
    const uint32_t al_base = sptr(Al) + (a_row * LDK + a_col) * 2;
    const uint32_t bh_base = sptr(Bh) + (b_row * LDK + b_col) * 2;
    const uint32_t bl_base = sptr(Bl) + (b_row * LDK + b_col) * 2;

    for (int kc = 0; kc < 4; ++kc) {
        __syncthreads();
#pragma unroll
        for (int it = 0; it < 32; ++it) {
            int idx = it * 384 + t;
            int k   = idx / 192;
            int pix = idx - k * 192;
            float v = guide[(size_t)b * C * PIX + (size_t)(kc * 64 + k) * PIX + p0 + pix];
            __nv_bfloat16 h = __float2bfloat16(v);
            __nv_bfloat16 l = __float2bfloat16(v - __bfloat162float(h));
            Ah[pix * LDK + k] = h;
            Al[pix * LDK + k] = l;
        }
        for (int idx = t; idx < 64 * 64; idx += 384) {
            int col = idx >> 6, r = idx & 63;
            float wv = W1[(size_t)col * C + kc * 64 + r];
            __nv_bfloat16 h = __float2bfloat16(wv);
            __nv_bfloat16 l = __float2bfloat16(wv - __bfloat162float(h));
            Bh[col * LDK + r] = h;
            Bl[col * LDK + r] = l;
        }
        __syncthreads();

#pragma unroll
        for (int ks = 0; ks < 4; ++ks) {
            const uint32_t ko = ks * 32;
            uint32_t ah[2][4], al[2][4];
#pragma unroll
            for (int mf = 0; mf < 2; ++mf) {
                ldmat_x4(ah[mf][0], ah[mf][1], ah[mf][2], ah[mf][3],
                         ah_base + mf * (16 * LDK * 2) + ko);
                ldmat_x4(al[mf][0], al[mf][1], al[mf][2], al[mf][3],
                         al_base + mf * (16 * LDK * 2) + ko);
            }
#pragma unroll
            for (int p = 0; p < 2; ++p) {
                uint32_t bh0, bh1, bh2, bh3, bl0, bl1, bl2, bl3;
                ldmat_x4(bh0, bh1, bh2, bh3, bh_base + p * (16 * LDK * 2) + ko);
                ldmat_x4(bl0, bl1, bl2, bl3, bl_base + p * (16 * LDK * 2) + ko);
#pragma unroll
                for (int mf = 0; mf < 2; ++mf) {
                    float* c0 = acc[mf][2 * p];
                    float* c1 = acc[mf][2 * p + 1];
                    mma_bf16(c0[0], c0[1], c0[2], c0[3],
                             ah[mf][0], ah[mf][1], ah[mf][2], ah[mf][3], bh0, bh1);
                    mma_bf16(c0[0], c0[1], c0[2], c0[3],
                             ah[mf][0], ah[mf][1], ah[mf][2], ah[mf][3], bl0, bl1);
                    mma_bf16(c0[0], c0[1], c0[2], c0[3],
                             al[mf][0], al[mf][1], al[mf][2], al[mf][3], bh0, bh1);
                    mma_bf16(c1[0], c1[1], c1[2], c1[3],
                             ah[mf][0], ah[mf][1], ah[mf][2], ah[mf][3], bh2, bh3);
                    mma_bf16(c1[0], c1[1], c1[2], c1[3],
                             ah[mf][0], ah[mf][1], ah[mf][2], ah[mf][3], bl2, bl3);
                    mma_bf16(c1[0], c1[1], c1[2], c1[3],
                             al[mf][0], al[mf][1], al[mf][2], al[mf][3], bh2, bh3);
                }
            }
        }
    }

    const int c2 = (lane & 3) * 2;
#pragma unroll
    for (int mf = 0; mf < 2; ++mf) {
        int pb = mw * 2 + mf;
#pragma unroll
        for (int nfp = 0; nfp < 2; ++nfp) {
            int kb = nw * 2 + nfp;
            uint32_t hi4[4], lo4[4];
#pragma unroll
            for (int j = 0; j < 4; ++j) {
                int nf  = 2 * nfp + (j >> 1);
                int col = nw * 32 + nf * 8 + c2;
                int q0  = 2 * (j & 1);
                float v0 = fmaxf(acc[mf][nf][q0]     * sc[col]     + bi[col],     0.f);
                float v1 = fmaxf(acc[mf][nf][q0 + 1] * sc[col + 1] + bi[col + 1], 0.f);
                split_pack(v0, v1, hi4[j], lo4[j]);
            }
            size_t blk = (((size_t)b * 48 + blockIdx.x) * 12 + pb) * 4 + kb;
            uint32_t* dh = g_xfh + blk * 128 + lane * 4;
            uint32_t* dl = g_xfl + blk * 128 + lane * 4;
            *(uint4*)dh = make_uint4(hi4[0], hi4[1], hi4[2], hi4[3]);
            *(uint4*)dl = make_uint4(lo4[0], lo4[1], lo4[2], lo4[3]);
        }
    }
}

// ---------------------------------------------------------------------------
// Kernel 2 (fused): per CTA = (row pair i0, group g, batch b). 256 threads.
//   ft staging issued FIRST (independent of mma; LDG latency hides under
//   tensor work), then zero-smem mma from fragment-packed gmem, then Ds
//   tap-major, ONE barrier, then 192-thread involution (R13 shape).
// grid (48, 16, 8), smem 91920B, 2 CTAs/SM.
// ---------------------------------------------------------------------------
#define F_FT_ROW 104
#define F_FT_CH  836                               // 8*104 + 4 (= 4 mod 32)
#define F_FT_PAR (8 * F_FT_CH)                     // 6688
#define F_FT_FLOATS (2 * F_FT_PAR)                 // 13376
#define F_DS_OFF    F_FT_FLOATS
#define F_DS_LD     196                             // tap stride (floats)
#define F_SMEM ((F_FT_FLOATS + KT2 * F_DS_LD) * 4)  // 91920 bytes

__global__ __launch_bounds__(256, 2) void k_fused(
    const float* __restrict__ feat, float* __restrict__ out)
{
    extern __shared__ __nv_bfloat16 sm[];
    float* ft = (float*)sm;                 // [2 par][8 u][8 rows][104]
    float* Ds = (float*)sm + F_DS_OFF;      // [49][196]

    const int t    = threadIdx.x;
    const int lane = t & 31;
    const int wid  = t >> 5;
    const int mw   = wid & 3;
    const int nw   = wid >> 2;
    const int b    = blockIdx.z;
    const int g    = blockIdx.y;
    const int i0   = blockIdx.x * 2;

    // ---- phase 0: ft staging FIRST (LDG latency overlaps the mma below) ----
    {
        const float* fg = feat + ((size_t)b * C + g * GC) * PIX;
#pragma unroll 8
        for (int it = 0; it < 64; ++it) {
            int idx = it * 256 + t;
            int cc  = idx & 127;
            int rr  = (idx >> 7) & 7;
            int ch  = idx >> 10;
            if (cc < 102) {
                int grow = i0 + rr - 3;
                int gcol = cc - 3;
                float v = 0.f;
                if (grow >= 0 && grow < HH && gcol >= 0 && gcol < WW)
                    v = fg[(size_t)ch * PIX + grow * WW + gcol];
                ft[(ch & 1) * F_FT_PAR + (ch >> 1) * F_FT_CH + rr * F_FT_ROW + cc] = v;
            }
        }
    }

    // ---- phase 1: mma; A and B fragments straight from gmem (zero smem) ----
    float acc[3][4][4];
#pragma unroll
    for (int mf = 0; mf < 3; ++mf)
#pragma unroll
        for (int nf = 0; nf < 4; ++nf)
#pragma unroll
            for (int q = 0; q < 4; ++q) acc[mf][nf][q] = 0.f;

    {
        const size_t tile = ((size_t)b * 48 + blockIdx.x) * 12;
        const uint4* xfh = (const uint4*)g_xfh + tile * 128;
        const uint4* xfl = (const uint4*)g_xfl + tile * 128;
        const uint2* wh  = g_w2h + g * 1024;
        const uint2* wl  = g_w2l + g * 1024;

#pragma unroll
        for (int ks = 0; ks < 4; ++ks) {
            uint32_t ah[3][4], al[3][4];
#pragma unroll
            for (int mf = 0; mf < 3; ++mf) {
                int pb = mw * 3 + mf;
                uint4 h4 = xfh[(pb * 4 + ks) * 32 + lane];
                uint4 l4 = xfl[(pb * 4 + ks) * 32 + lane];
                ah[mf][0] = h4.x; ah[mf][1] = h4.y; ah[mf][2] = h4.z; ah[mf][3] = h4.w;
                al[mf][0] = l4.x; al[mf][1] = l4.y; al[mf][2] = l4.z; al[mf][3] = l4.w;
            }
#pragma unroll
            for (int nf = 0; nf < 4; ++nf) {
                int fi = (ks * 8 + nw * 4 + nf) * 32 + lane;
                uint2 bh = wh[fi];
                uint2 bl = wl[fi];
#pragma unroll
                for (int mf = 0; mf < 3; ++mf) {
                    float* cc = acc[mf][nf];
                    mma_bf16(cc[0], cc[1], cc[2], cc[3],
                             ah[mf][0], ah[mf][1], ah[mf][2], ah[mf][3], bh.x, bh.y);
                    mma_bf16(cc[0], cc[1], cc[2], cc[3],
                             ah[mf][0], ah[mf][1], ah[mf][2], ah[mf][3], bl.x, bl.y);
                    mma_bf16(cc[0], cc[1], cc[2], cc[3],
                             al[mf][0], al[mf][1], al[mf][2], al[mf][3], bh.x, bh.y);
                }
            }
        }
    }

    // ---- phase 2: write Ds tap-major (cols<49) ----
    {
        const int ar = lane >> 2;
#pragma unroll
        for (int mf = 0; mf < 3; ++mf) {
            int row = mw * 48 + mf * 16 + ar;
#pragma unroll
            for (int nf = 0; nf < 4; ++nf) {
                int col = nw * 32 + nf * 8 + (lane & 3) * 2;
                if (col < KT2) {
                    Ds[col * F_DS_LD + row]     = acc[mf][nf][0];
                    Ds[col * F_DS_LD + row + 8] = acc[mf][nf][2];
                }
                if (col + 1 < KT2) {
                    Ds[(col + 1) * F_DS_LD + row]     = acc[mf][nf][1];
                    Ds[(col + 1) * F_DS_LD + row + 8] = acc[mf][nf][3];
                }
            }
        }
    }
    __syncthreads();

    // ---- phase 3: involution + residual (192 fat threads, R13 shape) ----
    if (t < 192) {
        const int u    = t & 7;
        const int s12  = t >> 3;
        const int team = s12 / 12;
        const int seg  = s12 - team * 12;
        const int jb   = 8 * seg;
        const int i    = i0 + team;
        const int ch0  = 2 * u;

        const float* ft0 = ft + u * F_FT_CH;
        const float* ft1 = ft + F_FT_PAR + u * F_FT_CH;
        const float* dk  = Ds + team * 96 + jb;

        float o0[8], o1[8];
#pragma unroll
        for (int jj = 0; jj < 8; ++jj) {
            o0[jj] = ft0[(team + 3) * F_FT_ROW + 3 + jb + jj];   // residual
            o1[jj] = ft1[(team + 3) * F_FT_ROW + 3 + jb + jj];
        }
#pragma unroll
        for (int di = 0; di < KT; ++di) {
            float f0[14], f1[14];
            const float* r0p = ft0 + (team + di) * F_FT_ROW + jb;
            const float* r1p = ft1 + (team + di) * F_FT_ROW + jb;
#pragma unroll
            for (int q = 0; q < 3; ++q) {
                float4 v0 = *(const float4*)(r0p + 4 * q);
                float4 v1 = *(const float4*)(r1p + 4 * q);
                f0[4*q] = v0.x; f0[4*q+1] = v0.y; f0[4*q+2] = v0.z; f0[4*q+3] = v0.w;
                f1[4*q] = v1.x; f1[4*q+1] = v1.y; f1[4*q+2] = v1.z; f1[4*q+3] = v1.w;
            }
            {
                float2 v0 = *(const float2*)(r0p + 12);
                float2 v1 = *(const float2*)(r1p + 12);
                f0[12] = v0.x; f0[13] = v0.y;
                f1[12] = v1.x; f1[13] = v1.y;
            }
#pragma unroll
            for (int dj = 0; dj < KT; ++dj) {
                const float* dp = dk + (di * KT + dj) * F_DS_LD;
                float4 d0 = *(const float4*)(dp);
                float4 d1 = *(const float4*)(dp + 4);
                o0[0] += f0[dj]     * d0.x;  o1[0] += f1[dj]     * d0.x;
                o0[1] += f0[dj + 1] * d0.y;  o1[1] += f1[dj + 1] * d0.y;
                o0[2] += f0[dj + 2] * d0.z;  o1[2] += f1[dj + 2] * d0.z;
                o0[3] += f0[dj + 3] * d0.w;  o1[3] += f1[dj + 3] * d0.w;
                o0[4] += f0[dj + 4] * d1.x;  o1[4] += f1[dj + 4] * d1.x;
                o0[5] += f0[dj + 5] * d1.y;  o1[5] += f1[dj + 5] * d1.y;
                o0[6] += f0[dj + 6] * d1.z;  o1[6] += f1[dj + 6] * d1.z;
                o0[7] += f0[dj + 7] * d1.w;  o1[7] += f1[dj + 7] * d1.w;
            }
        }
        size_t ob = (((size_t)b * C + g * GC + ch0) * HH + i) * WW + jb;
        *(float4*)(out + ob)           = make_float4(o0[0], o0[1], o0[2], o0[3]);
        *(float4*)(out + ob + 4)       = make_float4(o0[4], o0[5], o0[6], o0[7]);
        *(float4*)(out + ob + PIX)     = make_float4(o1[0], o1[1], o1[2], o1[3]);
        *(float4*)(out + ob + PIX + 4) = make_float4(o1[4], o1[5], o1[6], o1[7]);
    }
}

// ---------------------------------------------------------------------------
extern "C" void kernel_launch(void* const* d_in, const int* in_sizes, int n_in,
                              void* d_out, int out_size)
{
    const float* feat  = (const float*)d_in[0];
    const float* guide = (const float*)d_in[1];
    const float* W1    = (const float*)d_in[2];
    const float* gamma = (const float*)d_in[3];
    const float* beta  = (const float*)d_in[4];
    const float* mean  = (const float*)d_in[5];
    const float* var   = (const float*)d_in[6];
    const float* W2    = (const float*)d_in[7];
    float* out = (float*)d_out;

    cudaFuncSetAttribute(k_convs1, cudaFuncAttributeMaxDynamicSharedMemorySize, C1_SMEM);
    cudaFuncSetAttribute(k_fused,  cudaFuncAttributeMaxDynamicSharedMemorySize, F_SMEM);

    k_w2pack<<<NG, 256>>>(W2);
    k_convs1<<<dim3(48, 8), 384, C1_SMEM>>>(guide, W1, gamma, beta, mean, var);
    k_fused<<<dim3(48, 16, 8), 256, F_SMEM>>>(feat, out);
}

// round 16
// speedup vs baseline: 2.4036x; 2.4036x over previous
#include <cuda_runtime.h>
#include <cuda_bf16.h>
#include <cstdint>
#include <cstddef>

#define R 64        // reduced channels
#define C 256       // channels
#define HH 96
#define WW 96
#define PIX (HH*WW)
#define NG 16       // groups
#define GC 16       // group channels
#define KT 7
#define KT2 49

// x = relu(BN(W1 @ guide)) stored FRAGMENT-PACKED for m16n8k16 A-operands:
// [b][ptile 48][pixblock 12][kblock 4][lane 32][reg 4] (u32 = 2 bf16)
__device__ uint32_t g_xfh[(size_t)8 * 48 * 12 * 4 * 32 * 4];
__device__ uint32_t g_xfl[(size_t)8 * 48 * 12 * 4 * 32 * 4];

// W2 pre-packed as m16n8k16 B-fragments, hi/lo:
// [g][ks 4][ntile 8][lane 32] uint2 = {b0 (k,k+1), b1 (k+8,k+9)}
__device__ uint2 g_w2h[NG * 4 * 8 * 32];
__device__ uint2 g_w2l[NG * 4 * 8 * 32];

#define LDK 72                 // padded k-stride (bf16 elems) in smem tiles

// ---------------------------------------------------------------------------
// mma.sync m16n8k16 bf16 (row.col), fp32 accumulate (verified mapping, R5)
// ---------------------------------------------------------------------------
__device__ __forceinline__ void mma_bf16(
    float& c0, float& c1, float& c2, float& c3,
    uint32_t a0, uint32_t a1, uint32_t a2, uint32_t a3,
    uint32_t b0, uint32_t b1)
{
    asm volatile(
        "mma.sync.aligned.m16n8k16.row.col.f32.bf16.bf16.f32 "
        "{%0,%1,%2,%3}, {%4,%5,%6,%7}, {%8,%9}, {%0,%1,%2,%3};"
        : "+f"(c0), "+f"(c1), "+f"(c2), "+f"(c3)
        : "r"(a0), "r"(a1), "r"(a2), "r"(a3), "r"(b0), "r"(b1));
}
__device__ __forceinline__ void ldmat_x4(uint32_t& r0, uint32_t& r1,
                                         uint32_t& r2, uint32_t& r3, uint32_t a)
{
    asm volatile("ldmatrix.sync.aligned.m8n8.x4.shared.b16 {%0,%1,%2,%3}, [%4];"
                 : "=r"(r0), "=r"(r1), "=r"(r2), "=r"(r3) : "r"(a));
}
__device__ __forceinline__ uint32_t sptr(const void* p) {
    return (uint32_t)__cvta_generic_to_shared(p);
}
__device__ __forceinline__ void split_pack(float a, float b,
                                           uint32_t& hi, uint32_t& lo)
{
    __nv_bfloat162 h2 = __floats2bfloat162_rn(a, b);
    __nv_bfloat162 l2 = __floats2bfloat162_rn(
        a - __bfloat162float(h2.x), b - __bfloat162float(h2.y));
    hi = *(uint32_t*)&h2;
    lo = *(uint32_t*)&l2;
}

// ---------------------------------------------------------------------------
// Kernel 0: pack W2 into B-fragment layout (runs once per launch, ~4us)
// ---------------------------------------------------------------------------
__global__ void k_w2pack(const float* __restrict__ W2)
{
    int g = blockIdx.x, t = threadIdx.x;
#pragma unroll
    for (int it = 0; it < 4; ++it) {
        int idx  = it * 256 + t;             // (ks*8 + nt)*32 + lane
        int lane = idx & 31;
        int nt   = (idx >> 5) & 7;
        int ks   = idx >> 8;
        int col  = nt * 8 + (lane >> 2);
        int k    = ks * 16 + (lane & 3) * 2;
        float w00 = 0.f, w01 = 0.f, w10 = 0.f, w11 = 0.f;
        if (col < KT2) {
            const float* wp = W2 + ((size_t)g * KT2 + col) * R;
            w00 = wp[k];     w01 = wp[k + 1];
            w10 = wp[k + 8]; w11 = wp[k + 9];
        }
        uint32_t b0h, b0l, b1h, b1l;
        split_pack(w00, w01, b0h, b0l);
        split_pack(w10, w11, b1h, b1l);
        g_w2h[g * 1024 + idx] = make_uint2(b0h, b1h);
        g_w2l[g * 1024 + idx] = make_uint2(b0l, b1l);
    }
}

// ---------------------------------------------------------------------------
// Kernel 1: x = relu(BN(W1 @ guide)) via mma.sync, 3-term bf16 split.
// CTA: 384 thr = 12 warps (6M x 2N). D[192 pix][64 out], K=256 in 4 chunks.
// Epilogue: BN+ReLU + hi/lo split, FRAGMENT-PACKED coalesced STG.128.
// grid (48, 8), smem 72KB, 2 CTAs/SM.  [R13 verified, ~55us]
// ---------------------------------------------------------------------------
#define C1_AH 0
#define C1_AL (192 * LDK)
#define C1_BH (2 * 192 * LDK)
#define C1_BL (2 * 192 * LDK + 64 * LDK)
#define C1_SMEM ((2 * 192 * LDK + 2 * 64 * LDK) * 2)   // 73728 bytes

__global__ __launch_bounds__(384, 2) void k_convs1(
    const float* __restrict__ guide, const float* __restrict__ W1,
    const float* __restrict__ gamma, const float* __restrict__ beta,
    const float* __restrict__ mean,  const float* __restrict__ var)
{
    extern __shared__ __nv_bfloat16 sm[];
    __nv_bfloat16* Ah = sm + C1_AH;
    __nv_bfloat16* Al = sm + C1_AL;
    __nv_bfloat16* Bh = sm + C1_BH;
    __nv_bfloat16* Bl = sm + C1_BL;
    __shared__ float sc[R], bi[R];

    const int t    = threadIdx.x;
    const int lane = t & 31;
    const int wid  = t >> 5;
    const int mw   = wid >> 1;
    const int nw   = wid & 1;
    const int b    = blockIdx.y;
    const int p0   = blockIdx.x * 192;

    if (t < R) {
        float iv = gamma[t] * rsqrtf(var[t] + 1e-5f);
        sc[t] = iv;
        bi[t] = beta[t] - mean[t] * iv;
    }

    float acc[2][4][4];
#pragma unroll
    for (int mf = 0; mf < 2; ++mf)
#pragma unroll
        for (int nf = 0; nf < 4; ++nf)
#pragma unroll
            for (int q = 0; q < 4; ++q) acc[mf][nf][q] = 0.f;

    const int l7  = lane & 7;
    const int sub = lane >> 3;
    const int a_row = mw * 32 + (sub & 1) * 8 + l7;
    const int a_col = (sub >> 1) * 8;
    const int b_row = nw * 32 + (sub >> 1) * 8 + l7;
    const int b_col = (sub & 1) * 8;
    const uint32_t ah_base = sptr(Ah) + (a_row * LDK + a_col) * 2;
    const uint32_t al_base = sptr(Al) + (a_row * LDK + a_col) * 2;
    const uint32_t bh_base = sptr(Bh) + (b_row * LDK + b_col) * 2;
    const uint32_t bl_base = sptr(Bl) + (b_row * LDK + b_col) * 2;

    for (int kc = 0; kc < 4; ++kc) {
        __syncthreads();
#pragma unroll
        for (int it = 0; it < 32; ++it) {
            int idx = it * 384 + t;
            int k   = idx / 192;
            int pix = idx - k * 192;
            float v = guide[(size_t)b * C * PIX + (size_t)(kc * 64 + k) * PIX + p0 + pix];
            __nv_bfloat16 h = __float2bfloat16(v);
            __nv_bfloat16 l = __float2bfloat16(v - __bfloat162float(h));
            Ah[pix * LDK + k] = h;
            Al[pix * LDK + k] = l;
        }
        for (int idx = t; idx < 64 * 64; idx += 384) {
            int col = idx >> 6, r = idx & 63;
            float wv = W1[(size_t)col * C + kc * 64 + r];
            __nv_bfloat16 h = __float2bfloat16(wv);
            __nv_bfloat16 l = __float2bfloat16(wv - __bfloat162float(h));
            Bh[col * LDK + r] = h;
            Bl[col * LDK + r] = l;
        }
        __syncthreads();

#pragma unroll
        for (int ks = 0; ks < 4; ++ks) {
            const uint32_t ko = ks * 32;
            uint32_t ah[2][4], al[2][4];
#pragma unroll
            for (int mf = 0; mf < 2; ++mf) {
                ldmat_x4(ah[mf][0], ah[mf][1], ah[mf][2], ah[mf][3],
                         ah_base + mf * (16 * LDK * 2) + ko);
                ldmat_x4(al[mf][0], al[mf][1], al[mf][2], al[mf][3],
                         al_base + mf * (16 * LDK * 2) + ko);
            }
#pragma unroll
            for (int p = 0; p < 2; ++p) {
                uint32_t bh0, bh1, bh2, bh3, bl0, bl1, bl2, bl3;
                ldmat_x4(bh0, bh1, bh2, bh3, bh_base + p * (16 * LDK * 2) + ko);
                ldmat_x4(bl0, bl1, bl2, bl3, bl_base + p * (16 * LDK * 2) + ko);
#pragma unroll
                for (int mf = 0; mf < 2; ++mf) {
                    float* c0 = acc[mf][2 * p];
                    float* c1 = acc[mf][2 * p + 1];
                    mma_bf16(c0[0], c0[1], c0[2], c0[3],
                             ah[mf][0], ah[mf][1], ah[mf][2], ah[mf][3], bh0, bh1);
                    mma_bf16(c0[0], c0[1], c0[2], c0[3],
                             ah[mf][0], ah[mf][1], ah[mf][2], ah[mf][3], bl0, bl1);
                    mma_bf16(c0[0], c0[1], c0[2], c0[3],
                             al[mf][0], al[mf][1], al[mf][2], al[mf][3], bh0, bh1);
                    mma_bf16(c1[0], c1[1], c1[2], c1[3],
                             ah[mf][0], ah[mf][1], ah[mf][2], ah[mf][3], bh2, bh3);
                    mma_bf16(c1[0], c1[1], c1[2], c1[3],
                             ah[mf][0], ah[mf][1], ah[mf][2], ah[mf][3], bl2, bl3);
                    mma_bf16(c1[0], c1[1], c1[2], c1[3],
                             al[mf][0], al[mf][1], al[mf][2], al[mf][3], bh2, bh3);
                }
            }
        }
    }

    const int c2 = (lane & 3) * 2;
#pragma unroll
    for (int mf = 0; mf < 2; ++mf) {
        int pb = mw * 2 + mf;
#pragma unroll
        for (int nfp = 0; nfp < 2; ++nfp) {
            int kb = nw * 2 + nfp;
            uint32_t hi4[4], lo4[4];
#pragma unroll
            for (int j = 0; j < 4; ++j) {
                int nf  = 2 * nfp + (j >> 1);
                int col = nw * 32 + nf * 8 + c2;
                int q0  = 2 * (j & 1);
                float v0 = fmaxf(acc[mf][nf][q0]     * sc[col]     + bi[col],     0.f);
                float v1 = fmaxf(acc[mf][nf][q0 + 1] * sc[col + 1] + bi[col + 1], 0.f);
                split_pack(v0, v1, hi4[j], lo4[j]);
            }
            size_t blk = (((size_t)b * 48 + blockIdx.x) * 12 + pb) * 4 + kb;
            uint32_t* dh = g_xfh + blk * 128 + lane * 4;
            uint32_t* dl = g_xfl + blk * 128 + lane * 4;
            *(uint4*)dh = make_uint4(hi4[0], hi4[1], hi4[2], hi4[3]);
            *(uint4*)dl = make_uint4(lo4[0], lo4[1], lo4[2], lo4[3]);
        }
    }
}

// ---------------------------------------------------------------------------
// Kernel 2 (fused): per CTA = (row pair i0, group g, batch b). 256 threads.
//   Phase 1: df = x^T @ W2^g^T; A AND B fragments straight from gmem
//            (zero smem, zero ldmatrix, zero barriers in phase 1).
//   Phase 2: acc -> Ds[49][196] tap-major ; ft [2 par][8 u][8 rows][104]
//   Phase 3: 192 fat threads, LDS.128 f-loads + broadcast d-loads.
// grid (48, 16, 8), smem 91920B, 2 CTAs/SM. ONE barrier per CTA.
// [R13 verified, ~175us]
// ---------------------------------------------------------------------------
#define F_FT_ROW 104
#define F_FT_CH  836                               // 8*104 + 4 (= 4 mod 32)
#define F_FT_PAR (8 * F_FT_CH)                     // 6688
#define F_FT_FLOATS (2 * F_FT_PAR)                 // 13376
#define F_DS_OFF    F_FT_FLOATS
#define F_DS_LD     196                             // tap stride (floats)
#define F_SMEM ((F_FT_FLOATS + KT2 * F_DS_LD) * 4)  // 91920 bytes

__global__ __launch_bounds__(256, 2) void k_fused(
    const float* __restrict__ feat, float* __restrict__ out)
{
    extern __shared__ __nv_bfloat16 sm[];
    float* ft = (float*)sm;
    float* Ds = (float*)sm + F_DS_OFF;      // [49][196]

    const int t    = threadIdx.x;
    const int lane = t & 31;
    const int wid  = t >> 5;
    const int mw   = wid & 3;
    const int nw   = wid >> 2;
    const int b    = blockIdx.z;
    const int g    = blockIdx.y;
    const int i0   = blockIdx.x * 2;

    // ---- phase 1: mma; A and B fragments straight from gmem ----
    float acc[3][4][4];
#pragma unroll
    for (int mf = 0; mf < 3; ++mf)
#pragma unroll
        for (int nf = 0; nf < 4; ++nf)
#pragma unroll
            for (int q = 0; q < 4; ++q) acc[mf][nf][q] = 0.f;

    {
        const size_t tile = ((size_t)b * 48 + blockIdx.x) * 12;
        const uint4* xfh = (const uint4*)g_xfh + tile * 128;
        const uint4* xfl = (const uint4*)g_xfl + tile * 128;
        const uint2* wh  = g_w2h + g * 1024;
        const uint2* wl  = g_w2l + g * 1024;

#pragma unroll
        for (int ks = 0; ks < 4; ++ks) {
            uint32_t ah[3][4], al[3][4];
#pragma unroll
            for (int mf = 0; mf < 3; ++mf) {
                int pb = mw * 3 + mf;
                uint4 h4 = xfh[(pb * 4 + ks) * 32 + lane];
                uint4 l4 = xfl[(pb * 4 + ks) * 32 + lane];
                ah[mf][0] = h4.x; ah[mf][1] = h4.y; ah[mf][2] = h4.z; ah[mf][3] = h4.w;
                al[mf][0] = l4.x; al[mf][1] = l4.y; al[mf][2] = l4.z; al[mf][3] = l4.w;
            }
#pragma unroll
            for (int nf = 0; nf < 4; ++nf) {
                int fi = (ks * 8 + nw * 4 + nf) * 32 + lane;
                uint2 bh = wh[fi];
                uint2 bl = wl[fi];
#pragma unroll
                for (int mf = 0; mf < 3; ++mf) {
                    float* cc = acc[mf][nf];
                    mma_bf16(cc[0], cc[1], cc[2], cc[3],
                             ah[mf][0], ah[mf][1], ah[mf][2], ah[mf][3], bh.x, bh.y);
                    mma_bf16(cc[0], cc[1], cc[2], cc[3],
                             ah[mf][0], ah[mf][1], ah[mf][2], ah[mf][3], bl.x, bl.y);
                    mma_bf16(cc[0], cc[1], cc[2], cc[3],
                             al[mf][0], al[mf][1], al[mf][2], al[mf][3], bh.x, bh.y);
                }
            }
        }
    }

    // ---- phase 2: write Ds tap-major (cols<49) + stage ft (parity layout) ----
    {
        const int ar = lane >> 2;
#pragma unroll
        for (int mf = 0; mf < 3; ++mf) {
            int row = mw * 48 + mf * 16 + ar;
#pragma unroll
            for (int nf = 0; nf < 4; ++nf) {
                int col = nw * 32 + nf * 8 + (lane & 3) * 2;
                if (col < KT2) {
                    Ds[col * F_DS_LD + row]     = acc[mf][nf][0];
                    Ds[col * F_DS_LD + row + 8] = acc[mf][nf][2];
                }
                if (col + 1 < KT2) {
                    Ds[(col + 1) * F_DS_LD + row]     = acc[mf][nf][1];
                    Ds[(col + 1) * F_DS_LD + row + 8] = acc[mf][nf][3];
                }
            }
        }
    }
    {
        const float* fg = feat + ((size_t)b * C + g * GC) * PIX;
#pragma unroll
        for (int it = 0; it < 64; ++it) {
            int idx = it * 256 + t;
            int cc  = idx & 127;
            int rr  = (idx >> 7) & 7;
            int ch  = idx >> 10;
            if (cc < 102) {
                int grow = i0 + rr - 3;
                int gcol = cc - 3;
                float v = 0.f;
                if (grow >= 0 && grow < HH && gcol >= 0 && gcol < WW)
                    v = fg[(size_t)ch * PIX + grow * WW + gcol];
                ft[(ch & 1) * F_FT_PAR + (ch >> 1) * F_FT_CH + rr * F_FT_ROW + cc] = v;
            }
        }
    }
    __syncthreads();

    // ---- phase 3: involution + residual (192 fat threads) ----
    if (t < 192) {
        const int u    = t & 7;
        const int s12  = t >> 3;
        const int team = s12 / 12;
        const int seg  = s12 - team * 12;
        const int jb   = 8 * seg;
        const int i    = i0 + team;
        const int ch0  = 2 * u;

        const float* ft0 = ft + u * F_FT_CH;
        const float* ft1 = ft + F_FT_PAR + u * F_FT_CH;
        const float* dk  = Ds + team * 96 + jb;

        float o0[8], o1[8];
#pragma unroll
        for (int jj = 0; jj < 8; ++jj) {
            o0[jj] = ft0[(team + 3) * F_FT_ROW + 3 + jb + jj];   // residual
            o1[jj] = ft1[(team + 3) * F_FT_ROW + 3 + jb + jj];
        }
#pragma unroll
        for (int di = 0; di < KT; ++di) {
            float f0[14], f1[14];
            const float* r0p = ft0 + (team + di) * F_FT_ROW + jb;
            const float* r1p = ft1 + (team + di) * F_FT_ROW + jb;
#pragma unroll
            for (int q = 0; q < 3; ++q) {
                float4 v0 = *(const float4*)(r0p + 4 * q);
                float4 v1 = *(const float4*)(r1p + 4 * q);
                f0[4*q] = v0.x; f0[4*q+1] = v0.y; f0[4*q+2] = v0.z; f0[4*q+3] = v0.w;
                f1[4*q] = v1.x; f1[4*q+1] = v1.y; f1[4*q+2] = v1.z; f1[4*q+3] = v1.w;
            }
            {
                float2 v0 = *(const float2*)(r0p + 12);
                float2 v1 = *(const float2*)(r1p + 12);
                f0[12] = v0.x; f0[13] = v0.y;
                f1[12] = v1.x; f1[13] = v1.y;
            }
#pragma unroll
            for (int dj = 0; dj < KT; ++dj) {
                const float* dp = dk + (di * KT + dj) * F_DS_LD;
                float4 d0 = *(const float4*)(dp);
                float4 d1 = *(const float4*)(dp + 4);
                o0[0] += f0[dj]     * d0.x;  o1[0] += f1[dj]     * d0.x;
                o0[1] += f0[dj + 1] * d0.y;  o1[1] += f1[dj + 1] * d0.y;
                o0[2] += f0[dj + 2] * d0.z;  o1[2] += f1[dj + 2] * d0.z;
                o0[3] += f0[dj + 3] * d0.w;  o1[3] += f1[dj + 3] * d0.w;
                o0[4] += f0[dj + 4] * d1.x;  o1[4] += f1[dj + 4] * d1.x;
                o0[5] += f0[dj + 5] * d1.y;  o1[5] += f1[dj + 5] * d1.y;
                o0[6] += f0[dj + 6] * d1.z;  o1[6] += f1[dj + 6] * d1.z;
                o0[7] += f0[dj + 7] * d1.w;  o1[7] += f1[dj + 7] * d1.w;
            }
        }
        size_t ob = (((size_t)b * C + g * GC + ch0) * HH + i) * WW + jb;
        *(float4*)(out + ob)           = make_float4(o0[0], o0[1], o0[2], o0[3]);
        *(float4*)(out + ob + 4)       = make_float4(o0[4], o0[5], o0[6], o0[7]);
        *(float4*)(out + ob + PIX)     = make_float4(o1[0], o1[1], o1[2], o1[3]);
        *(float4*)(out + ob + PIX + 4) = make_float4(o1[4], o1[5], o1[6], o1[7]);
    }
}

// ---------------------------------------------------------------------------
extern "C" void kernel_launch(void* const* d_in, const int* in_sizes, int n_in,
                              void* d_out, int out_size)
{
    const float* feat  = (const float*)d_in[0];
    const float* guide = (const float*)d_in[1];
    const float* W1    = (const float*)d_in[2];
    const float* gamma = (const float*)d_in[3];
    const float* beta  = (const float*)d_in[4];
    const float* mean  = (const float*)d_in[5];
    const float* var   = (const float*)d_in[6];
    const float* W2    = (const float*)d_in[7];
    float* out = (float*)d_out;

    cudaFuncSetAttribute(k_convs1, cudaFuncAttributeMaxDynamicSharedMemorySize, C1_SMEM);
    cudaFuncSetAttribute(k_fused,  cudaFuncAttributeMaxDynamicSharedMemorySize, F_SMEM);

    k_w2pack<<<NG, 256>>>(W2);
    k_convs1<<<dim3(48, 8), 384, C1_SMEM>>>(guide, W1, gamma, beta, mean, var);
    k_fused<<<dim3(48, 16, 8), 256, F_SMEM>>>(feat, out);
}